// round 3
// baseline (speedup 1.0000x reference)
#include <cuda_runtime.h>

// ProbAttention (Informer ProbSparse) for B=2, L=4096, H=8, D=64, sample_k = n_top = 45.
// Pipeline: zero-out + idx detect/convert | scoring M | top-k | split-KV sparse attention | combine.

#define Bb   2
#define Ll   4096
#define Hh   8
#define Dd   64
#define SSK  45          // sample_k == n_top
#define BH   (Bb*Hh)     // 16
#define NC   16          // kv chunks in phase 3
#define CK   256         // keys per chunk (NC*CK == Ll)

// ---- scratch (static device globals: no allocation allowed) ----
__device__ int    g_idx_is64;
__device__ int    g_idx32[Ll * SSK];
__device__ float  g_M[BH * Ll];
__device__ int    g_top[BH * SSK];
__device__ float  g_pmax[BH * NC * SSK];
__device__ float  g_psum[BH * NC * SSK];
__device__ float4 g_pout[BH * NC * SSK * (Dd / 4)];

// ---------------- K0a: zero output ----------------
__global__ void k0_zero(float4* __restrict__ out4, int n4) {
    int i = blockIdx.x * 256 + threadIdx.x;
    if (i < n4) out4[i] = make_float4(0.f, 0.f, 0.f, 0.f);
}

// ---------------- K0b: detect index dtype (int32 vs int64) ----------------
// Indices are in [0, 4096). If the buffer is int64, every odd 32-bit word is 0.
// If it is int32, odd words are random indices (all-zero prob = 4096^-128 ~ 0).
__global__ void k0_detect(const unsigned* __restrict__ src) {
    __shared__ int nz;
    if (threadIdx.x == 0) nz = 0;
    __syncthreads();
    unsigned v = src[threadIdx.x * 2 + 1];   // first 128 odd words (< 184320 either way)
    if (v != 0u) atomicAdd(&nz, 1);
    __syncthreads();
    if (threadIdx.x == 0) g_idx_is64 = (nz == 0) ? 1 : 0;
}

// ---------------- K0c: normalize indices -> int32 ----------------
__global__ void k0_cvt(const void* __restrict__ src, int n) {
    int i = blockIdx.x * 256 + threadIdx.x;
    if (i < n) {
        if (g_idx_is64) g_idx32[i] = (int)((const long long*)src)[i];
        else            g_idx32[i] = ((const int*)src)[i];
    }
}

// ---------------- K1: sampled scores M ----------------
// One warp per (b,l), processing ALL 8 heads at once.
// Lane layout: lane covers floats [lane*16, lane*16+16) of the 512-float (H*D) row,
// so lanes {4h..4h+3} own head h. Per-sample: 2KB key row load + 16 FMA + 2 shfl.
__global__ __launch_bounds__(256) void k1_score(const float4* __restrict__ q4,
                                                const float4* __restrict__ k4) {
    int w    = blockIdx.x * 8 + (threadIdx.x >> 5);   // (b,l) id, 0..8191
    int lane = threadIdx.x & 31;
    int b = w >> 12;
    int l = w & (Ll - 1);

    const float4* qp = q4 + (size_t)(b * Ll + l) * (Hh * Dd / 4) + lane * 4;
    float4 qv0 = qp[0], qv1 = qp[1], qv2 = qp[2], qv3 = qp[3];

    float mx = -1e30f, sm = 0.f;
    const int* ip = g_idx32 + l * SSK;

    #pragma unroll 3
    for (int s = 0; s < SSK; s++) {
        int idx = ip[s];   // uniform across warp
        const float4* kp = k4 + (size_t)(b * Ll + idx) * (Hh * Dd / 4) + lane * 4;
        float4 a = kp[0], c = kp[1], e = kp[2], f = kp[3];
        float p = qv0.x*a.x + qv0.y*a.y + qv0.z*a.z + qv0.w*a.w;
        p += qv1.x*c.x + qv1.y*c.y + qv1.z*c.z + qv1.w*c.w;
        p += qv2.x*e.x + qv2.y*e.y + qv2.z*e.z + qv2.w*e.w;
        p += qv3.x*f.x + qv3.y*f.y + qv3.z*f.z + qv3.w*f.w;
        // reduce within 4-lane head group
        p += __shfl_xor_sync(0xffffffffu, p, 1);
        p += __shfl_xor_sync(0xffffffffu, p, 2);
        mx = fmaxf(mx, p);
        sm += p;
    }
    if ((lane & 3) == 0) {
        int h = lane >> 2;
        g_M[(b * Hh + h) * Ll + l] = mx - sm * (1.0f / (float)Ll);
    }
}

// ---------------- K2: top-45 per (b,h) ----------------
__device__ __forceinline__ unsigned long long packfi(float f, int idx) {
    unsigned u = __float_as_uint(f);
    u = (u & 0x80000000u) ? ~u : (u | 0x80000000u);   // order-preserving map
    return ((unsigned long long)u << 32) | (unsigned)idx;
}

__global__ __launch_bounds__(256) void k2_topk() {
    int bh  = blockIdx.x;
    int tid = threadIdx.x;

    float v[16];
    #pragma unroll
    for (int i = 0; i < 16; i++) v[i] = g_M[bh * Ll + i * 256 + tid];

    unsigned used = 0;
    unsigned long long best = 0ull;
    #pragma unroll
    for (int i = 0; i < 16; i++) {
        unsigned long long pk = packfi(v[i], i * 256 + tid);
        if (pk > best) best = pk;
    }

    __shared__ unsigned long long sm64[9];

    for (int r = 0; r < SSK; r++) {
        unsigned long long pk = best;
        #pragma unroll
        for (int o = 16; o; o >>= 1) {
            unsigned long long oth = __shfl_xor_sync(0xffffffffu, pk, o);
            if (oth > pk) pk = oth;
        }
        if ((tid & 31) == 0) sm64[tid >> 5] = pk;
        __syncthreads();
        if (tid < 32) {
            unsigned long long q = (tid < 8) ? sm64[tid] : 0ull;
            #pragma unroll
            for (int o = 4; o; o >>= 1) {
                unsigned long long oth = __shfl_xor_sync(0xffffffffu, q, o);
                if (oth > q) q = oth;
            }
            if (tid == 0) {
                sm64[8] = q;
                g_top[bh * SSK + r] = (int)(q & 0xffffffffu);
            }
        }
        __syncthreads();
        int widx = (int)(sm64[8] & 0xffffffffu);
        if ((widx & 255) == tid) {        // owner removes it and rescans
            used |= 1u << (widx >> 8);
            best = 0ull;
            #pragma unroll
            for (int i = 0; i < 16; i++) {
                if (!((used >> i) & 1u)) {
                    unsigned long long pk2 = packfi(v[i], i * 256 + tid);
                    if (pk2 > best) best = pk2;
                }
            }
        }
        __syncthreads();
    }
}

// ---------------- K3: split-KV sparse attention partials ----------------
// Grid (NC, BH). Each CTA: 256 threads, keys [c*CK, c*CK+CK).
// smem: qs[45*64] | ks[256*64] (XOR-swizzled, reused for V) | ss[45*256] | tops[45]
#define K3_SMEM ((SSK*Dd + CK*Dd + SSK*CK) * 4 + 256)

__global__ __launch_bounds__(256) void k3_attn(const float4* __restrict__ q4,
                                               const float4* __restrict__ k4g,
                                               const float4* __restrict__ v4g) {
    int c  = blockIdx.x;
    int bh = blockIdx.y;
    int b = bh >> 3, h = bh & 7;
    int tid = threadIdx.x;

    extern __shared__ float smem[];
    float*  qs   = smem;                  // 2880 floats
    float*  ks   = qs + SSK * Dd;         // 16384 floats
    float*  ss   = ks + CK * Dd;          // 11520 floats
    int*    tops = (int*)(ss + SSK * CK); // 45 ints
    float4* qs4  = (float4*)qs;
    float4* ks4  = (float4*)ks;

    if (tid < SSK) tops[tid] = g_top[bh * SSK + tid];
    __syncthreads();

    // stage selected Q rows (broadcast-read later: no swizzle needed)
    for (int i = tid; i < SSK * (Dd / 4); i += 256) {
        int u = i >> 4, c4 = i & 15;
        qs4[i] = q4[((size_t)(b * Ll + tops[u]) * Hh + h) * (Dd / 4) + c4];
    }
    // stage K chunk, XOR-swizzled at float4 granularity
    int k0 = c * CK;
    for (int i = tid; i < CK * (Dd / 4); i += 256) {
        int row = i >> 4, c4 = i & 15;
        ks4[row * 16 + (c4 ^ (row & 7))] =
            k4g[((size_t)(b * Ll + k0 + row) * Hh + h) * (Dd / 4) + c4];
    }
    __syncthreads();

    // S-phase: thread j = key index, computes S[u][j] for all 45 u
    float acc[SSK];
    #pragma unroll
    for (int u = 0; u < SSK; u++) acc[u] = 0.f;
    int j = tid;
    #pragma unroll
    for (int dc = 0; dc < 4; dc++) {
        float4 kr[4];
        #pragma unroll
        for (int w = 0; w < 4; w++) kr[w] = ks4[j * 16 + ((dc * 4 + w) ^ (j & 7))];
        #pragma unroll
        for (int u = 0; u < SSK; u++) {
            #pragma unroll
            for (int w = 0; w < 4; w++) {
                float4 qv = qs4[u * 16 + dc * 4 + w];   // warp-broadcast LDS
                acc[u] += qv.x*kr[w].x + qv.y*kr[w].y + qv.z*kr[w].z + qv.w*kr[w].w;
            }
        }
    }
    #pragma unroll
    for (int u = 0; u < SSK; u++) ss[u * CK + j] = acc[u];
    __syncthreads();

    // partial softmax per row u (warp-per-row)
    int wid = tid >> 5, lane = tid & 31;
    for (int u = wid; u < SSK; u += 8) {
        float x[8];
        float mx = -1e30f;
        #pragma unroll
        for (int t = 0; t < 8; t++) { x[t] = ss[u * CK + lane + t * 32]; mx = fmaxf(mx, x[t]); }
        #pragma unroll
        for (int o = 16; o; o >>= 1) mx = fmaxf(mx, __shfl_xor_sync(0xffffffffu, mx, o));
        float sum = 0.f;
        #pragma unroll
        for (int t = 0; t < 8; t++) { float p = __expf(0.125f * (x[t] - mx)); x[t] = p; sum += p; }
        #pragma unroll
        for (int o = 16; o; o >>= 1) sum += __shfl_xor_sync(0xffffffffu, sum, o);
        #pragma unroll
        for (int t = 0; t < 8; t++) ss[u * CK + lane + t * 32] = x[t];
        if (lane == 0) {
            g_pmax[(bh * NC + c) * SSK + u] = 0.125f * mx;  // scaled-domain row max
            g_psum[(bh * NC + c) * SSK + u] = sum;
        }
    }
    __syncthreads();

    // stage V chunk into the K buffer (same swizzle)
    for (int i = tid; i < CK * (Dd / 4); i += 256) {
        int row = i >> 4, c4 = i & 15;
        ks4[row * 16 + (c4 ^ (row & 7))] =
            v4g[((size_t)(b * Ll + k0 + row) * Hh + h) * (Dd / 4) + c4];
    }
    __syncthreads();

    // P@V: thread = (u-group, d4). 16 u per pass x 3 passes.
    int d4 = tid & 15, ug = tid >> 4;
    #pragma unroll
    for (int p = 0; p < 3; p++) {
        int u = ug + p * 16;
        if (u < SSK) {
            float4 a = make_float4(0.f, 0.f, 0.f, 0.f);
            #pragma unroll 8
            for (int jj = 0; jj < CK; jj++) {
                float pw  = ss[u * CK + jj];                      // 2-way broadcast
                float4 vv = ks4[jj * 16 + (d4 ^ (jj & 7))];       // conflict-free perm
                a.x += pw * vv.x; a.y += pw * vv.y;
                a.z += pw * vv.z; a.w += pw * vv.w;
            }
            g_pout[((bh * NC + c) * SSK + u) * 16 + d4] = a;
        }
    }
}

// ---------------- K4: combine partials + scatter ----------------
__global__ __launch_bounds__(256) void k4_combine(float4* __restrict__ out4) {
    int bh = blockIdx.x;
    int b = bh >> 3, h = bh & 7;
    for (int i = threadIdx.x; i < SSK * 16; i += 256) {
        int u = i >> 4, d4 = i & 15;
        float gm = -1e30f;
        #pragma unroll
        for (int cc = 0; cc < NC; cc++)
            gm = fmaxf(gm, g_pmax[(bh * NC + cc) * SSK + u]);
        float denom = 0.f;
        float4 a = make_float4(0.f, 0.f, 0.f, 0.f);
        #pragma unroll
        for (int cc = 0; cc < NC; cc++) {
            float w = __expf(g_pmax[(bh * NC + cc) * SSK + u] - gm);
            denom += g_psum[(bh * NC + cc) * SSK + u] * w;
            float4 po = g_pout[((bh * NC + cc) * SSK + u) * 16 + d4];
            a.x += w * po.x; a.y += w * po.y; a.z += w * po.z; a.w += w * po.w;
        }
        float inv = 1.0f / denom;
        a.x *= inv; a.y *= inv; a.z *= inv; a.w *= inv;
        int lsel = g_top[bh * SSK + u];
        out4[((size_t)(b * Ll + lsel) * Hh + h) * 16 + d4] = a;
    }
}

// ---------------- launch ----------------
extern "C" void kernel_launch(void* const* d_in, const int* in_sizes, int n_in,
                              void* d_out, int out_size) {
    const float4* q4 = (const float4*)d_in[0];
    const float4* k4 = (const float4*)d_in[1];
    const float4* v4 = (const float4*)d_in[2];
    // Locate index_sample by element count (robust to small-input reordering).
    const void* idxp = d_in[n_in - 1];
    for (int i = 0; i < n_in; i++)
        if (in_sizes[i] == Ll * SSK) idxp = d_in[i];
    float4* out4 = (float4*)d_out;

    cudaFuncSetAttribute(k3_attn, cudaFuncAttributeMaxDynamicSharedMemorySize, K3_SMEM);

    int n4 = out_size / 4;
    k0_zero<<<(n4 + 255) / 256, 256>>>(out4, n4);
    k0_detect<<<1, 128>>>((const unsigned*)idxp);
    k0_cvt<<<(Ll * SSK + 255) / 256, 256>>>(idxp, Ll * SSK);
    k1_score<<<Bb * Ll / 8, 256>>>(q4, k4);
    k2_topk<<<BH, 256>>>();
    k3_attn<<<dim3(NC, BH), 256, K3_SMEM>>>(q4, k4, v4);
    k4_combine<<<BH, 256>>>(out4);
}

// round 4
// speedup vs baseline: 1.3248x; 1.3248x over previous
#include <cuda_runtime.h>

// ProbAttention (Informer ProbSparse) for B=2, L=4096, H=8, D=64, sample_k = n_top = 45.

#define Bb   2
#define Ll   4096
#define Hh   8
#define Dd   64
#define SSK  45          // sample_k == n_top
#define BH   (Bb*Hh)     // 16
#define NC   16          // kv chunks in phase 3
#define CK   256         // keys per chunk (NC*CK == Ll)
#define SST  257         // padded ss row stride (floats)

typedef unsigned long long ull;

// ---- scratch (static device globals: no allocation allowed) ----
__device__ int    g_idx_is64;
__device__ int    g_idx32[Ll * SSK];
__device__ float  g_M[BH * Ll];
__device__ int    g_top[BH * SSK];
__device__ float  g_pmax[BH * NC * SSK];
__device__ float  g_psum[BH * NC * SSK];
__device__ float4 g_pout[BH * NC * SSK * (Dd / 4)];

// ---- f32x2 packed-FMA helpers ----
__device__ __forceinline__ ull fma2(ull a, ull b, ull c) {
    ull d;
    asm("fma.rn.f32x2 %0, %1, %2, %3;" : "=l"(d) : "l"(a), "l"(b), "l"(c));
    return d;
}
__device__ __forceinline__ ull pack2(float x, float y) {
    ull r;
    asm("mov.b64 %0, {%1, %2};" : "=l"(r) : "f"(x), "f"(y));
    return r;
}
__device__ __forceinline__ void unpack2(ull v, float& x, float& y) {
    asm("mov.b64 {%0, %1}, %2;" : "=f"(x), "=f"(y) : "l"(v));
}

// ---------------- K0a: zero output ----------------
__global__ void k0_zero(float4* __restrict__ out4, int n4) {
    int i = blockIdx.x * 256 + threadIdx.x;
    if (i < n4) out4[i] = make_float4(0.f, 0.f, 0.f, 0.f);
}

// ---------------- K0b: detect index dtype (int32 vs int64) ----------------
__global__ void k0_detect(const unsigned* __restrict__ src) {
    __shared__ int nz;
    if (threadIdx.x == 0) nz = 0;
    __syncthreads();
    unsigned v = src[threadIdx.x * 2 + 1];
    if (v != 0u) atomicAdd(&nz, 1);
    __syncthreads();
    if (threadIdx.x == 0) g_idx_is64 = (nz == 0) ? 1 : 0;
}

// ---------------- K0c: normalize indices -> int32 ----------------
__global__ void k0_cvt(const void* __restrict__ src, int n) {
    int i = blockIdx.x * 256 + threadIdx.x;
    if (i < n) {
        if (g_idx_is64) g_idx32[i] = (int)((const long long*)src)[i];
        else            g_idx32[i] = ((const int*)src)[i];
    }
}

// ---------------- K1: sampled scores M ----------------
// One warp per (b,l). Coalesced: LDG t reads float4 index (32t + lane) -> 512B
// contiguous per LDG (4 L1 wavefronts). Chunk c = 32t+lane belongs to head
// h = 2t + (lane>>4); reduce over the 16-lane half with 4 shfl_xor.
__global__ __launch_bounds__(256) void k1_score(const float4* __restrict__ q4,
                                                const float4* __restrict__ k4) {
    int w    = blockIdx.x * 8 + (threadIdx.x >> 5);
    int lane = threadIdx.x & 31;
    int b = w >> 12;
    int l = w & (Ll - 1);

    const float4* qp = q4 + (size_t)(b * Ll + l) * (Hh * Dd / 4);
    float4 qv[4];
    #pragma unroll
    for (int t = 0; t < 4; t++) qv[t] = qp[t * 32 + lane];

    float mx[4] = {-1e30f, -1e30f, -1e30f, -1e30f};
    float sm[4] = {0.f, 0.f, 0.f, 0.f};
    const int* ip = g_idx32 + l * SSK;

    #pragma unroll 2
    for (int s = 0; s < SSK; s++) {
        const float4* kp = k4 + (size_t)(b * Ll + ip[s]) * (Hh * Dd / 4);
        #pragma unroll
        for (int t = 0; t < 4; t++) {
            float4 kv = kp[t * 32 + lane];
            float p = qv[t].x*kv.x + qv[t].y*kv.y + qv[t].z*kv.z + qv[t].w*kv.w;
            p += __shfl_xor_sync(0xffffffffu, p, 8);
            p += __shfl_xor_sync(0xffffffffu, p, 4);
            p += __shfl_xor_sync(0xffffffffu, p, 2);
            p += __shfl_xor_sync(0xffffffffu, p, 1);
            mx[t] = fmaxf(mx[t], p);
            sm[t] += p;
        }
    }
    if ((lane & 15) == 0) {
        int half = lane >> 4;
        #pragma unroll
        for (int t = 0; t < 4; t++) {
            int h = 2 * t + half;
            g_M[(b * Hh + h) * Ll + l] = mx[t] - sm[t] * (1.0f / (float)Ll);
        }
    }
}

// ---------------- K2: top-45 per (b,h) ----------------
__device__ __forceinline__ ull packfi(float f, int idx) {
    unsigned u = __float_as_uint(f);
    u = (u & 0x80000000u) ? ~u : (u | 0x80000000u);   // order-preserving map
    return ((ull)u << 32) | (unsigned)idx;
}

// Phase 1: each warp extracts its sorted top-45 of its 512 elements (no CTA
// barriers inside the rounds). Phase 2: warp 0 merges the 8 sorted lists.
__global__ __launch_bounds__(256) void k2_topk() {
    int bh  = blockIdx.x;
    int tid = threadIdx.x;
    int wid = tid >> 5, lane = tid & 31;

    __shared__ ull lists[8][SSK];

    float v[16];
    int base = bh * Ll + wid * 512 + lane;
    #pragma unroll
    for (int i = 0; i < 16; i++) v[i] = g_M[base + 32 * i];

    unsigned used = 0;
    ull best = 0ull;
    #pragma unroll
    for (int i = 0; i < 16; i++) {
        ull pk = packfi(v[i], wid * 512 + lane + 32 * i);
        if (pk > best) best = pk;
    }

    for (int r = 0; r < SSK; r++) {
        ull pk = best;
        #pragma unroll
        for (int o = 16; o; o >>= 1) {
            ull t = __shfl_xor_sync(0xffffffffu, pk, o);
            if (t > pk) pk = t;
        }
        if (lane == 0) lists[wid][r] = pk;
        if (pk == best) {   // unique owner (idx embedded -> keys distinct)
            int i_rm = (int)(((unsigned)(pk & 0xffffffffu) - (unsigned)(wid * 512 + lane)) >> 5);
            used |= 1u << i_rm;
            best = 0ull;
            #pragma unroll
            for (int i = 0; i < 16; i++) {
                if (!((used >> i) & 1u)) {
                    ull p2 = packfi(v[i], wid * 512 + lane + 32 * i);
                    if (p2 > best) best = p2;
                }
            }
        }
    }
    __syncthreads();

    if (wid == 0) {
        ull cur = (lane < 8) ? lists[lane][0] : 0ull;
        int p = 1;
        for (int r = 0; r < SSK; r++) {
            ull m = cur;
            #pragma unroll
            for (int o = 4; o; o >>= 1) {
                ull t = __shfl_xor_sync(0xffffffffu, m, o);
                if (t > m) m = t;
            }
            if (lane < 8 && cur == m) {
                g_top[bh * SSK + r] = (int)(m & 0xffffffffu);
                cur = (p < SSK) ? lists[lane][p] : 0ull;
                p++;
            }
        }
    }
}

// ---------------- K3: split-KV sparse attention partials ----------------
// smem: qs2 (u-pair packed Q, 23x128 floats) | ks (256x64, swizzled, reused
// for V) | ss (45 x 257 padded) | tops
#define QS2F (23 * 128)
#define K3_SMEM ((QS2F + CK * Dd + SSK * SST) * 4 + 256)

// One S-phase pass over NI u-pairs starting at pair index I0.
template <int NI>
__device__ __forceinline__ void s_pass(int i0, int j, const float4* ks4,
                                       const ulonglong2* qsU, float* ss) {
    ull acc[NI];
    #pragma unroll
    for (int i = 0; i < NI; i++) acc[i] = 0ull;

    #pragma unroll 1
    for (int dc = 0; dc < 16; dc++) {
        float4 kr = ks4[j * 16 + (dc ^ (j & 7))];
        ull kk0 = pack2(kr.x, kr.x);
        ull kk1 = pack2(kr.y, kr.y);
        ull kk2 = pack2(kr.z, kr.z);
        ull kk3 = pack2(kr.w, kr.w);
        #pragma unroll
        for (int i = 0; i < NI; i++) {
            ulonglong2 qA = qsU[(i0 + i) * 32 + dc * 2];      // d = 4dc, 4dc+1
            ulonglong2 qB = qsU[(i0 + i) * 32 + dc * 2 + 1];  // d = 4dc+2, 4dc+3
            acc[i] = fma2(qA.x, kk0, acc[i]);
            acc[i] = fma2(qA.y, kk1, acc[i]);
            acc[i] = fma2(qB.x, kk2, acc[i]);
            acc[i] = fma2(qB.y, kk3, acc[i]);
        }
    }
    #pragma unroll
    for (int i = 0; i < NI; i++) {
        float lo, hi;
        unpack2(acc[i], lo, hi);
        int u = 2 * (i0 + i);
        ss[u * SST + j] = lo;
        if (u + 1 < SSK) ss[(u + 1) * SST + j] = hi;
    }
}

__global__ __launch_bounds__(256) void k3_attn(const float4* __restrict__ q4,
                                               const float4* __restrict__ k4g,
                                               const float4* __restrict__ v4g) {
    int c  = blockIdx.x;
    int bh = blockIdx.y;
    int b = bh >> 3, h = bh & 7;
    int tid = threadIdx.x;

    extern __shared__ float smem[];
    float* qs2f = smem;                   // 23*128 floats (u-pair packed Q)
    float* ks   = qs2f + QS2F;            // 16384 floats
    float* ss   = ks + CK * Dd;           // 45*257 floats
    int*   tops = (int*)(ss + SSK * SST);
    float4*           ks4 = (float4*)ks;
    const ulonglong2* ksU = (const ulonglong2*)ks;
    const ulonglong2* qsU = (const ulonglong2*)qs2f;

    if (tid < SSK) tops[tid] = g_top[bh * SSK + tid];
    __syncthreads();

    // stage Q in u-pair-packed layout: qs2f[(i*128 + 2d) + o] = q[2i+o][d]
    for (int i = tid; i < 46 * 16; i += 256) {
        int u = i >> 4, c4 = i & 15;
        float4 qv = (u < SSK)
            ? q4[((size_t)(b * Ll + tops[u]) * Hh + h) * (Dd / 4) + c4]
            : make_float4(0.f, 0.f, 0.f, 0.f);
        float* dst = qs2f + ((u >> 1) * 128 + 8 * c4) + (u & 1);
        dst[0] = qv.x; dst[2] = qv.y; dst[4] = qv.z; dst[6] = qv.w;
    }
    // stage K chunk, XOR-swizzled at float4 granularity
    int k0 = c * CK;
    for (int i = tid; i < CK * (Dd / 4); i += 256) {
        int row = i >> 4, c4 = i & 15;
        ks4[row * 16 + (c4 ^ (row & 7))] =
            k4g[((size_t)(b * Ll + k0 + row) * Hh + h) * (Dd / 4) + c4];
    }
    __syncthreads();

    // S-phase: thread j computes S[u][j] for all 45 u, two passes of u-pairs
    s_pass<12>(0,  tid, ks4, qsU, ss);
    s_pass<11>(12, tid, ks4, qsU, ss);
    __syncthreads();

    // partial softmax per row u (warp-per-row)
    int wid = tid >> 5, lane = tid & 31;
    for (int u = wid; u < SSK; u += 8) {
        float x[8];
        float mx = -1e30f;
        #pragma unroll
        for (int t = 0; t < 8; t++) { x[t] = ss[u * SST + lane + t * 32]; mx = fmaxf(mx, x[t]); }
        #pragma unroll
        for (int o = 16; o; o >>= 1) mx = fmaxf(mx, __shfl_xor_sync(0xffffffffu, mx, o));
        float sum = 0.f;
        #pragma unroll
        for (int t = 0; t < 8; t++) { float p = __expf(0.125f * (x[t] - mx)); x[t] = p; sum += p; }
        #pragma unroll
        for (int o = 16; o; o >>= 1) sum += __shfl_xor_sync(0xffffffffu, sum, o);
        #pragma unroll
        for (int t = 0; t < 8; t++) ss[u * SST + lane + t * 32] = x[t];
        if (lane == 0) {
            g_pmax[(bh * NC + c) * SSK + u] = 0.125f * mx;
            g_psum[(bh * NC + c) * SSK + u] = sum;
        }
    }
    __syncthreads();

    // stage V chunk into the K buffer (same swizzle)
    for (int i = tid; i < CK * (Dd / 4); i += 256) {
        int row = i >> 4, c4 = i & 15;
        ks4[row * 16 + (c4 ^ (row & 7))] =
            v4g[((size_t)(b * Ll + k0 + row) * Hh + h) * (Dd / 4) + c4];
    }
    __syncthreads();

    // P@V: thread = (ug, d4); ug in [0,15) owns u = {3ug, 3ug+1, 3ug+2}
    int d4 = tid & 15, ug = tid >> 4;
    if (ug < 15) {
        int u0 = ug * 3;
        ull a0l = 0, a0h = 0, a1l = 0, a1h = 0, a2l = 0, a2h = 0;
        #pragma unroll 4
        for (int jj = 0; jj < CK; jj++) {
            ulonglong2 vv = ksU[jj * 16 + (d4 ^ (jj & 7))];
            ull P0 = pack2(ss[u0 * SST + jj],       ss[u0 * SST + jj]);
            ull P1 = pack2(ss[(u0 + 1) * SST + jj], ss[(u0 + 1) * SST + jj]);
            ull P2 = pack2(ss[(u0 + 2) * SST + jj], ss[(u0 + 2) * SST + jj]);
            a0l = fma2(P0, vv.x, a0l);  a0h = fma2(P0, vv.y, a0h);
            a1l = fma2(P1, vv.x, a1l);  a1h = fma2(P1, vv.y, a1h);
            a2l = fma2(P2, vv.x, a2l);  a2h = fma2(P2, vv.y, a2h);
        }
        ulonglong2* po = (ulonglong2*)g_pout;
        size_t baseo = ((size_t)(bh * NC + c) * SSK) * 16 + d4;
        po[baseo + (size_t)u0 * 16]       = make_ulonglong2(a0l, a0h);
        po[baseo + (size_t)(u0 + 1) * 16] = make_ulonglong2(a1l, a1h);
        po[baseo + (size_t)(u0 + 2) * 16] = make_ulonglong2(a2l, a2h);
    }
}

// ---------------- K4: combine partials + scatter ----------------
__global__ __launch_bounds__(256) void k4_combine(float4* __restrict__ out4) {
    int bh = blockIdx.x;
    int b = bh >> 3, h = bh & 7;
    for (int i = threadIdx.x; i < SSK * 16; i += 256) {
        int u = i >> 4, d4 = i & 15;
        float gm = -1e30f;
        #pragma unroll
        for (int cc = 0; cc < NC; cc++)
            gm = fmaxf(gm, g_pmax[(bh * NC + cc) * SSK + u]);
        float denom = 0.f;
        float4 a = make_float4(0.f, 0.f, 0.f, 0.f);
        #pragma unroll
        for (int cc = 0; cc < NC; cc++) {
            float w = __expf(g_pmax[(bh * NC + cc) * SSK + u] - gm);
            denom += g_psum[(bh * NC + cc) * SSK + u] * w;
            float4 po = g_pout[((bh * NC + cc) * SSK + u) * 16 + d4];
            a.x += w * po.x; a.y += w * po.y; a.z += w * po.z; a.w += w * po.w;
        }
        float inv = 1.0f / denom;
        a.x *= inv; a.y *= inv; a.z *= inv; a.w *= inv;
        int lsel = g_top[bh * SSK + u];
        out4[((size_t)(b * Ll + lsel) * Hh + h) * 16 + d4] = a;
    }
}

// ---------------- launch ----------------
extern "C" void kernel_launch(void* const* d_in, const int* in_sizes, int n_in,
                              void* d_out, int out_size) {
    const float4* q4 = (const float4*)d_in[0];
    const float4* k4 = (const float4*)d_in[1];
    const float4* v4 = (const float4*)d_in[2];
    const void* idxp = d_in[n_in - 1];
    for (int i = 0; i < n_in; i++)
        if (in_sizes[i] == Ll * SSK) idxp = d_in[i];
    float4* out4 = (float4*)d_out;

    cudaFuncSetAttribute(k3_attn, cudaFuncAttributeMaxDynamicSharedMemorySize, K3_SMEM);

    int n4 = out_size / 4;
    k0_zero<<<(n4 + 255) / 256, 256>>>(out4, n4);
    k0_detect<<<1, 128>>>((const unsigned*)idxp);
    k0_cvt<<<(Ll * SSK + 255) / 256, 256>>>(idxp, Ll * SSK);
    k1_score<<<Bb * Ll / 8, 256>>>(q4, k4);
    k2_topk<<<BH, 256>>>();
    k3_attn<<<dim3(NC, BH), 256, K3_SMEM>>>(q4, k4, v4);
    k4_combine<<<BH, 256>>>(out4);
}